// round 2
// baseline (speedup 1.0000x reference)
#include <cuda_runtime.h>
#include <cstdint>
#include <cstddef>

#define NN   8192
#define DIN  512
#define DH   256
#define DOUT 128
#define CAP  256
#define SLOPE 0.25f

// ---- scratch (static device globals; no allocation allowed) ----
__device__ int   g_cols[(size_t)NN * CAP];
__device__ float g_vals[(size_t)NN * CAP];
__device__ int   g_nnz[NN];
__device__ float g_bufA[(size_t)NN * DH];
__device__ float g_bufB[(size_t)NN * DH];
__device__ float g_h[(size_t)NN * DOUT];
__device__ float g_s1[NN];
__device__ float g_s2[NN];
__device__ float g_hmean[DOUT];

__device__ __forceinline__ float leaky(float x) { return x >= 0.f ? x : SLOPE * x; }

// ---------------------------------------------------------------------------
// Build padded CSR from dense adj. One block per row, 256 threads.
// Thread t owns 32 consecutive columns (one 128B line), kept in registers,
// block-wide exclusive scan gives sorted (by column) in-order edge list.
// ---------------------------------------------------------------------------
__global__ void build_csr(const float* __restrict__ adj) {
    int row = blockIdx.x;
    int t   = threadIdx.x;
    const float4* arow = reinterpret_cast<const float4*>(adj + (size_t)row * NN) + t * 8;

    float4 v[8];
    int cnt = 0;
#pragma unroll
    for (int i = 0; i < 8; i++) {
        v[i] = arow[i];
        cnt += (v[i].x > 0.f) + (v[i].y > 0.f) + (v[i].z > 0.f) + (v[i].w > 0.f);
    }

    __shared__ int sc[256];
    sc[t] = cnt;
    __syncthreads();
    // Hillis-Steele inclusive scan
    for (int off = 1; off < 256; off <<= 1) {
        int u = (t >= off) ? sc[t - off] : 0;
        __syncthreads();
        sc[t] += u;
        __syncthreads();
    }
    if (t == 255) g_nnz[row] = sc[255] < CAP ? sc[255] : CAP;

    int pos = sc[t] - cnt;
    int*   cr = g_cols + (size_t)row * CAP;
    float* vr = g_vals + (size_t)row * CAP;
    int base = t * 32;
#pragma unroll
    for (int i = 0; i < 8; i++) {
        float vv[4] = { v[i].x, v[i].y, v[i].z, v[i].w };
#pragma unroll
        for (int j = 0; j < 4; j++) {
            if (vv[j] > 0.f) {
                if (pos < CAP) { cr[pos] = base + i * 4 + j; vr[pos] = vv[j]; }
                pos++;
            }
        }
    }
}

// ---------------------------------------------------------------------------
// fp32 SGEMM, 128x128 block tile, BK=8, 8x8 per-thread micro-tile, 256 thr.
// All dims divide tile sizes (M=8192, N in {256,128}, K in {512,256}).
// ---------------------------------------------------------------------------
__global__ __launch_bounds__(256) void sgemm128(
    const float* __restrict__ A, const float* __restrict__ B,
    float* __restrict__ C, int K, int N)
{
    __shared__ __align__(16) float As[8][132];  // [k][m], padded: conflict-free
    __shared__ __align__(16) float Bs[8][128];  // [k][n]

    int tid = threadIdx.x;
    int tx = tid & 15, ty = tid >> 4;
    int m0 = blockIdx.y * 128, n0 = blockIdx.x * 128;

    float acc[8][8];
#pragma unroll
    for (int i = 0; i < 8; i++)
#pragma unroll
        for (int j = 0; j < 8; j++) acc[i][j] = 0.f;

    for (int k0 = 0; k0 < K; k0 += 8) {
#pragma unroll
        for (int i = 0; i < 4; i++) {
            int e = tid + i * 256;            // 128x8 A tile
            As[e & 7][e >> 3] = A[(size_t)(m0 + (e >> 3)) * K + k0 + (e & 7)];
        }
#pragma unroll
        for (int i = 0; i < 4; i++) {
            int e = tid + i * 256;            // 8x128 B tile
            Bs[e >> 7][e & 127] = B[(size_t)(k0 + (e >> 7)) * N + n0 + (e & 127)];
        }
        __syncthreads();
#pragma unroll
        for (int k = 0; k < 8; k++) {
            float4 a0 = *reinterpret_cast<const float4*>(&As[k][ty * 8]);
            float4 a1 = *reinterpret_cast<const float4*>(&As[k][ty * 8 + 4]);
            float4 b0 = *reinterpret_cast<const float4*>(&Bs[k][tx * 8]);
            float4 b1 = *reinterpret_cast<const float4*>(&Bs[k][tx * 8 + 4]);
            float ra[8] = { a0.x, a0.y, a0.z, a0.w, a1.x, a1.y, a1.z, a1.w };
            float rb[8] = { b0.x, b0.y, b0.z, b0.w, b1.x, b1.y, b1.z, b1.w };
#pragma unroll
            for (int i = 0; i < 8; i++)
#pragma unroll
                for (int j = 0; j < 8; j++) acc[i][j] += ra[i] * rb[j];
        }
        __syncthreads();
    }

#pragma unroll
    for (int i = 0; i < 8; i++) {
        size_t off = (size_t)(m0 + ty * 8 + i) * N + n0 + tx * 8;
        float4 o0 = { acc[i][0], acc[i][1], acc[i][2], acc[i][3] };
        float4 o1 = { acc[i][4], acc[i][5], acc[i][6], acc[i][7] };
        *reinterpret_cast<float4*>(&C[off])     = o0;
        *reinterpret_cast<float4*>(&C[off + 4]) = o1;
    }
}

// ---------------------------------------------------------------------------
// Sparse row-gather SpMM + bias + leaky.  O[row,:] = leaky(sum_e v_e*T[c_e,:]+b)
// One block (256 thr = DH columns) per row.
// ---------------------------------------------------------------------------
__global__ void spmm_leaky(const float* __restrict__ T,
                           const float* __restrict__ bias,
                           float* __restrict__ O)
{
    int row = blockIdx.x, t = threadIdx.x;
    int nnz = g_nnz[row];
    __shared__ int   sc[CAP];
    __shared__ float sv[CAP];
    for (int k = t; k < nnz; k += 256) {
        sc[k] = g_cols[(size_t)row * CAP + k];
        sv[k] = g_vals[(size_t)row * CAP + k];
    }
    __syncthreads();
    float acc = 0.f;
    for (int k = 0; k < nnz; k++)
        acc += sv[k] * T[(size_t)sc[k] * DH + t];
    O[(size_t)row * DH + t] = leaky(acc + bias[t]);
}

// s1[i] = dot(h[i], a[0:128]);  s2[i] = dot(h[i], a[128:256])
__global__ void scores_k(const float* __restrict__ a) {
    int row = blockIdx.x, t = threadIdx.x;   // 128 threads
    float hv = g_h[(size_t)row * DOUT + t];
    __shared__ float r1[128], r2[128];
    r1[t] = hv * a[t];
    r2[t] = hv * a[DOUT + t];
    __syncthreads();
    for (int s = 64; s > 0; s >>= 1) {
        if (t < s) { r1[t] += r1[t + s]; r2[t] += r2[t + s]; }
        __syncthreads();
    }
    if (t == 0) { g_s1[row] = r1[0]; g_s2[row] = r2[0]; }
}

// Column means of h (fallback for the measure-zero empty-row case)
__global__ void hmean_k() {
    int c = blockIdx.x, t = threadIdx.x;     // 128 blocks x 256 threads
    float s = 0.f;
    for (int r = t; r < NN; r += 256) s += g_h[(size_t)r * DOUT + c];
    __shared__ float red[256];
    red[t] = s;
    __syncthreads();
    for (int ss = 128; ss > 0; ss >>= 1) {
        if (t < ss) red[t] += red[t + ss];
        __syncthreads();
    }
    if (t == 0) g_hmean[c] = red[0] / (float)NN;
}

// ---------------------------------------------------------------------------
// Sparse attention row: e = leaky(s1[i]+s2[j]) on edges, softmax over edges
// (exactly matches dense masked softmax: exp(-1e12 - max) == 0.0f in fp32),
// h' = att @ h, out = leaky(h').  One block (128 thr = DOUT) per row.
// ---------------------------------------------------------------------------
__global__ void attn_k(float* __restrict__ out) {
    int row = blockIdx.x, t = threadIdx.x;   // 128 threads
    int nnz = g_nnz[row];
    __shared__ float w[CAP];
    __shared__ int   c[CAP];
    __shared__ float red[128];
    float o;
    if (nnz == 0) {
        // all-masked row: softmax is uniform 1/N -> mean of h
        o = leaky(g_hmean[t]);
    } else {
        float s1i = g_s1[row];
        for (int k = t; k < nnz; k += 128) {
            int cj = g_cols[(size_t)row * CAP + k];
            c[k] = cj;
            w[k] = leaky(s1i + g_s2[cj]);
        }
        __syncthreads();
        float m = -3.0e38f;
        for (int k = t; k < nnz; k += 128) m = fmaxf(m, w[k]);
        red[t] = m;
        __syncthreads();
        for (int s = 64; s > 0; s >>= 1) {
            if (t < s) red[t] = fmaxf(red[t], red[t + s]);
            __syncthreads();
        }
        float rmax = red[0];
        __syncthreads();
        float ssum = 0.f;
        for (int k = t; k < nnz; k += 128) {
            float e = expf(w[k] - rmax);
            w[k] = e;
            ssum += e;
        }
        red[t] = ssum;
        __syncthreads();
        for (int s = 64; s > 0; s >>= 1) {
            if (t < s) red[t] += red[t + s];
            __syncthreads();
        }
        float inv = 1.f / red[0];
        float acc = 0.f;
        for (int k = 0; k < nnz; k++)
            acc += w[k] * g_h[(size_t)c[k] * DOUT + t];
        o = leaky(acc * inv);
    }
    // output: mu = out[:, :64] flattened first, then logvar = out[:, 64:]
    if (t < 64) out[(size_t)row * 64 + t] = o;
    else        out[(size_t)NN * 64 + (size_t)row * 64 + (t - 64)] = o;
}

// ---------------------------------------------------------------------------
extern "C" void kernel_launch(void* const* d_in, const int* in_sizes, int n_in,
                              void* d_out, int out_size)
{
    const float* x   = (const float*)d_in[0];
    const float* adj = (const float*)d_in[1];
    const float* W1  = (const float*)d_in[2];
    const float* b1  = (const float*)d_in[3];
    const float* W2  = (const float*)d_in[4];
    const float* b2  = (const float*)d_in[5];
    const float* Wg  = (const float*)d_in[6];
    const float* a   = (const float*)d_in[7];

    float *pA, *pB, *pH;
    cudaGetSymbolAddress((void**)&pA, g_bufA);
    cudaGetSymbolAddress((void**)&pB, g_bufB);
    cudaGetSymbolAddress((void**)&pH, g_h);

    build_csr<<<NN, 256>>>(adj);

    // t1 = x @ W1
    sgemm128<<<dim3(DH / 128, NN / 128), 256>>>(x, W1, pA, DIN, DH);
    // x1 = leaky(adj @ t1 + b1)
    spmm_leaky<<<NN, 256>>>(pA, b1, pB);
    // t2 = x1 @ W2
    sgemm128<<<dim3(DH / 128, NN / 128), 256>>>(pB, W2, pA, DH, DH);
    // x2 = leaky(adj @ t2 + b2)
    spmm_leaky<<<NN, 256>>>(pA, b2, pB);
    // h = x2 @ Wg
    sgemm128<<<dim3(DOUT / 128, NN / 128), 256>>>(pB, Wg, pH, DH, DOUT);

    scores_k<<<NN, 128>>>(a);
    hmean_k<<<DOUT, 256>>>();
    attn_k<<<NN, 128>>>((float*)d_out);
}

// round 4
// speedup vs baseline: 1.1801x; 1.1801x over previous
#include <cuda_runtime.h>
#include <cstdint>
#include <cstddef>

#define NN   8192
#define DIN  512
#define DH   256
#define DOUT 128
#define CAP  256
#define SLOPE 0.25f

// ---- scratch (static device globals; no allocation allowed) ----
__device__ int   g_cols[(size_t)NN * CAP];
__device__ float g_vals[(size_t)NN * CAP];
__device__ int   g_nnz[NN];
__device__ float g_bufA[(size_t)NN * DH];
__device__ float g_bufB[(size_t)NN * DH];
__device__ float g_h[(size_t)NN * DOUT];
__device__ float g_s1[NN];
__device__ float g_s2[NN];
__device__ float g_hmean[DOUT];

__device__ __forceinline__ float leaky(float x) { return x >= 0.f ? x : SLOPE * x; }

// ---------------------------------------------------------------------------
// Build padded CSR from dense adj. One block per row, 256 threads.
// ---------------------------------------------------------------------------
__global__ void build_csr(const float* __restrict__ adj) {
    int row = blockIdx.x;
    int t   = threadIdx.x;
    const float4* arow = reinterpret_cast<const float4*>(adj + (size_t)row * NN) + t * 8;

    float4 v[8];
    int cnt = 0;
#pragma unroll
    for (int i = 0; i < 8; i++) {
        v[i] = arow[i];
        cnt += (v[i].x > 0.f) + (v[i].y > 0.f) + (v[i].z > 0.f) + (v[i].w > 0.f);
    }

    __shared__ int sc[256];
    sc[t] = cnt;
    __syncthreads();
    for (int off = 1; off < 256; off <<= 1) {
        int u = (t >= off) ? sc[t - off] : 0;
        __syncthreads();
        sc[t] += u;
        __syncthreads();
    }
    if (t == 255) g_nnz[row] = sc[255] < CAP ? sc[255] : CAP;

    int pos = sc[t] - cnt;
    int*   cr = g_cols + (size_t)row * CAP;
    float* vr = g_vals + (size_t)row * CAP;
    int base = t * 32;
#pragma unroll
    for (int i = 0; i < 8; i++) {
        float vv[4] = { v[i].x, v[i].y, v[i].z, v[i].w };
#pragma unroll
        for (int j = 0; j < 4; j++) {
            if (vv[j] > 0.f) {
                if (pos < CAP) { cr[pos] = base + i * 4 + j; vr[pos] = vv[j]; }
                pos++;
            }
        }
    }
}

// ---------------------------------------------------------------------------
// fp32 SGEMM, 128x128 tile, BK=8, double-buffered smem, reg-staged prefetch.
// 256 threads, 8x8 microtile, 2 CTAs/SM (<=128 regs).
// ---------------------------------------------------------------------------
__global__ __launch_bounds__(256, 2) void sgemm128(
    const float* __restrict__ A, const float* __restrict__ B,
    float* __restrict__ C, int K, int N)
{
    __shared__ __align__(16) float As[2][8][132];
    __shared__ __align__(16) float Bs[2][8][128];

    int tid = threadIdx.x;
    int tx = tid & 15, ty = tid >> 4;
    int m0 = blockIdx.y * 128, n0 = blockIdx.x * 128;

    // A stage: thread loads float4 at (row = tid>>1, k = 4*(tid&1))
    int arow = tid >> 1;
    int aq   = (tid & 1) * 4;
    const float* Aptr = A + (size_t)(m0 + arow) * K + aq;
    // B stage: thread loads float4 at (k = tid>>5, col = 4*(tid&31))
    int bk   = tid >> 5;
    int bcol = (tid & 31) * 4;
    const float* Bptr = B + (size_t)bk * N + n0 + bcol;

    // prologue: tile 0 -> buf 0
    float4 av = *reinterpret_cast<const float4*>(Aptr);
    float4 bv = *reinterpret_cast<const float4*>(Bptr);
    As[0][aq + 0][arow] = av.x; As[0][aq + 1][arow] = av.y;
    As[0][aq + 2][arow] = av.z; As[0][aq + 3][arow] = av.w;
    *reinterpret_cast<float4*>(&Bs[0][bk][bcol]) = bv;
    __syncthreads();

    float acc[8][8];
#pragma unroll
    for (int i = 0; i < 8; i++)
#pragma unroll
        for (int j = 0; j < 8; j++) acc[i][j] = 0.f;

    int ktiles = K >> 3;
    for (int tk = 0; tk < ktiles; tk++) {
        int buf = tk & 1;
        if (tk + 1 < ktiles) {
            av = *reinterpret_cast<const float4*>(Aptr + (tk + 1) * 8);
            bv = *reinterpret_cast<const float4*>(Bptr + (size_t)(tk + 1) * 8 * N);
        }
#pragma unroll
        for (int k = 0; k < 8; k++) {
            float4 a0 = *reinterpret_cast<const float4*>(&As[buf][k][ty * 8]);
            float4 a1 = *reinterpret_cast<const float4*>(&As[buf][k][ty * 8 + 4]);
            float4 b0 = *reinterpret_cast<const float4*>(&Bs[buf][k][tx * 8]);
            float4 b1 = *reinterpret_cast<const float4*>(&Bs[buf][k][tx * 8 + 4]);
            float ra[8] = { a0.x, a0.y, a0.z, a0.w, a1.x, a1.y, a1.z, a1.w };
            float rb[8] = { b0.x, b0.y, b0.z, b0.w, b1.x, b1.y, b1.z, b1.w };
#pragma unroll
            for (int i = 0; i < 8; i++)
#pragma unroll
                for (int j = 0; j < 8; j++) acc[i][j] += ra[i] * rb[j];
        }
        if (tk + 1 < ktiles) {
            int nb = buf ^ 1;
            As[nb][aq + 0][arow] = av.x; As[nb][aq + 1][arow] = av.y;
            As[nb][aq + 2][arow] = av.z; As[nb][aq + 3][arow] = av.w;
            *reinterpret_cast<float4*>(&Bs[nb][bk][bcol]) = bv;
        }
        __syncthreads();
    }

#pragma unroll
    for (int i = 0; i < 8; i++) {
        size_t off = (size_t)(m0 + ty * 8 + i) * N + n0 + tx * 8;
        float4 o0 = { acc[i][0], acc[i][1], acc[i][2], acc[i][3] };
        float4 o1 = { acc[i][4], acc[i][5], acc[i][6], acc[i][7] };
        *reinterpret_cast<float4*>(&C[off])     = o0;
        *reinterpret_cast<float4*>(&C[off + 4]) = o1;
    }
}

// ---------------------------------------------------------------------------
// Sparse row-gather SpMM + bias + leaky, float2 lanes, dual accumulators.
// One block (128 thr = 256 cols as float2) per row.
// ---------------------------------------------------------------------------
__global__ void spmm_leaky(const float* __restrict__ T,
                           const float* __restrict__ bias,
                           float* __restrict__ O)
{
    int row = blockIdx.x, t = threadIdx.x;     // 128 threads
    int nnz = g_nnz[row];
    __shared__ int   sc[CAP];
    __shared__ float sv[CAP];
    for (int k = t; k < nnz; k += 128) {
        sc[k] = g_cols[(size_t)row * CAP + k];
        sv[k] = g_vals[(size_t)row * CAP + k];
    }
    __syncthreads();
    float2 a0 = {0.f, 0.f}, a1 = {0.f, 0.f};
    int k = 0;
    for (; k + 1 < nnz; k += 2) {
        float2 v0 = reinterpret_cast<const float2*>(T + (size_t)sc[k]     * DH)[t];
        float2 v1 = reinterpret_cast<const float2*>(T + (size_t)sc[k + 1] * DH)[t];
        float w0 = sv[k], w1 = sv[k + 1];
        a0.x += w0 * v0.x; a0.y += w0 * v0.y;
        a1.x += w1 * v1.x; a1.y += w1 * v1.y;
    }
    if (k < nnz) {
        float2 v0 = reinterpret_cast<const float2*>(T + (size_t)sc[k] * DH)[t];
        float w0 = sv[k];
        a0.x += w0 * v0.x; a0.y += w0 * v0.y;
    }
    float2 b = reinterpret_cast<const float2*>(bias)[t];
    float2 o = { leaky(a0.x + a1.x + b.x), leaky(a0.y + a1.y + b.y) };
    reinterpret_cast<float2*>(O + (size_t)row * DH)[t] = o;
}

// s1[i] = dot(h[i], a[0:128]);  s2[i] = dot(h[i], a[128:256])
__global__ void scores_k(const float* __restrict__ a) {
    int row = blockIdx.x, t = threadIdx.x;   // 128 threads
    float hv = g_h[(size_t)row * DOUT + t];
    __shared__ float r1[128], r2[128];
    r1[t] = hv * a[t];
    r2[t] = hv * a[DOUT + t];
    __syncthreads();
    for (int s = 64; s > 0; s >>= 1) {
        if (t < s) { r1[t] += r1[t + s]; r2[t] += r2[t + s]; }
        __syncthreads();
    }
    if (t == 0) { g_s1[row] = r1[0]; g_s2[row] = r2[0]; }
}

// Column means of h (fallback for the measure-zero empty-row case)
__global__ void hmean_k() {
    int c = blockIdx.x, t = threadIdx.x;
    float s = 0.f;
    for (int r = t; r < NN; r += 256) s += g_h[(size_t)r * DOUT + c];
    __shared__ float red[256];
    red[t] = s;
    __syncthreads();
    for (int ss = 128; ss > 0; ss >>= 1) {
        if (t < ss) red[t] += red[t + ss];
        __syncthreads();
    }
    if (t == 0) g_hmean[c] = red[0] / (float)NN;
}

// ---------------------------------------------------------------------------
// Sparse attention row: exact match of dense masked softmax on edges.
// ---------------------------------------------------------------------------
__global__ void attn_k(float* __restrict__ out) {
    int row = blockIdx.x, t = threadIdx.x;   // 128 threads
    int nnz = g_nnz[row];
    __shared__ float w[CAP];
    __shared__ int   c[CAP];
    __shared__ float red[128];
    float o;
    if (nnz == 0) {
        o = leaky(g_hmean[t]);
    } else {
        float s1i = g_s1[row];
        for (int k = t; k < nnz; k += 128) {
            int cj = g_cols[(size_t)row * CAP + k];
            c[k] = cj;
            w[k] = leaky(s1i + g_s2[cj]);
        }
        __syncthreads();
        float m = -3.0e38f;
        for (int k = t; k < nnz; k += 128) m = fmaxf(m, w[k]);
        red[t] = m;
        __syncthreads();
        for (int s = 64; s > 0; s >>= 1) {
            if (t < s) red[t] = fmaxf(red[t], red[t + s]);
            __syncthreads();
        }
        float rmax = red[0];
        __syncthreads();
        float ssum = 0.f;
        for (int k = t; k < nnz; k += 128) {
            float e = expf(w[k] - rmax);
            w[k] = e;
            ssum += e;
        }
        red[t] = ssum;
        __syncthreads();
        for (int s = 64; s > 0; s >>= 1) {
            if (t < s) red[t] += red[t + s];
            __syncthreads();
        }
        float inv = 1.f / red[0];
        float acc0 = 0.f, acc1 = 0.f;
        int k = 0;
        for (; k + 1 < nnz; k += 2) {
            acc0 += w[k]     * g_h[(size_t)c[k]     * DOUT + t];
            acc1 += w[k + 1] * g_h[(size_t)c[k + 1] * DOUT + t];
        }
        if (k < nnz) acc0 += w[k] * g_h[(size_t)c[k] * DOUT + t];
        o = leaky((acc0 + acc1) * inv);
    }
    if (t < 64) out[(size_t)row * 64 + t] = o;
    else        out[(size_t)NN * 64 + (size_t)row * 64 + (t - 64)] = o;
}

// ---------------------------------------------------------------------------
extern "C" void kernel_launch(void* const* d_in, const int* in_sizes, int n_in,
                              void* d_out, int out_size)
{
    const float* x   = (const float*)d_in[0];
    const float* adj = (const float*)d_in[1];
    const float* W1  = (const float*)d_in[2];
    const float* b1  = (const float*)d_in[3];
    const float* W2  = (const float*)d_in[4];
    const float* b2  = (const float*)d_in[5];
    const float* Wg  = (const float*)d_in[6];
    const float* a   = (const float*)d_in[7];

    float *pA, *pB, *pH;
    cudaGetSymbolAddress((void**)&pA, g_bufA);
    cudaGetSymbolAddress((void**)&pB, g_bufB);
    cudaGetSymbolAddress((void**)&pH, g_h);

    build_csr<<<NN, 256>>>(adj);

    // t1 = x @ W1
    sgemm128<<<dim3(DH / 128, NN / 128), 256>>>(x, W1, pA, DIN, DH);
    // x1 = leaky(adj @ t1 + b1)
    spmm_leaky<<<NN, 128>>>(pA, b1, pB);
    // t2 = x1 @ W2
    sgemm128<<<dim3(DH / 128, NN / 128), 256>>>(pB, W2, pA, DH, DH);
    // x2 = leaky(adj @ t2 + b2)
    spmm_leaky<<<NN, 128>>>(pA, b2, pB);
    // h = x2 @ Wg
    sgemm128<<<dim3(DOUT / 128, NN / 128), 256>>>(pB, Wg, pH, DH, DOUT);

    scores_k<<<NN, 128>>>(a);
    hmean_k<<<DOUT, 256>>>();
    attn_k<<<NN, 128>>>((float*)d_out);
}

// round 5
// speedup vs baseline: 1.3030x; 1.1041x over previous
#include <cuda_runtime.h>
#include <cstdint>
#include <cstddef>

#define NN   8192
#define DIN  512
#define DH   256
#define DOUT 128
#define CAP  256
#define SLOPE 0.25f
#define FULL 0xffffffffu

// ---- scratch (static device globals; no allocation allowed) ----
__device__ int   g_cols[(size_t)NN * CAP];
__device__ float g_vals[(size_t)NN * CAP];
__device__ int   g_nnz[NN];
__device__ float g_bufA[(size_t)NN * DH];
__device__ float g_bufB[(size_t)NN * DH];
__device__ float g_h[(size_t)NN * DOUT];
__device__ float g_s1[NN];
__device__ float g_s2[NN];
__device__ float g_hmean[DOUT];

__device__ __forceinline__ float leaky(float x) { return x >= 0.f ? x : SLOPE * x; }

// ---------------------------------------------------------------------------
// Build padded CSR. One block/row, 256 thr; warp-scan (2 block syncs total).
// ---------------------------------------------------------------------------
__global__ void build_csr(const float* __restrict__ adj) {
    int row = blockIdx.x;
    int t   = threadIdx.x;
    int lane = t & 31, warp = t >> 5;
    const float4* arow = reinterpret_cast<const float4*>(adj + (size_t)row * NN) + t * 8;

    float4 v[8];
    int cnt = 0;
#pragma unroll
    for (int i = 0; i < 8; i++) {
        v[i] = arow[i];
        cnt += (v[i].x > 0.f) + (v[i].y > 0.f) + (v[i].z > 0.f) + (v[i].w > 0.f);
    }

    // warp inclusive scan
    int inc = cnt;
#pragma unroll
    for (int o = 1; o < 32; o <<= 1) {
        int u = __shfl_up_sync(FULL, inc, o);
        if (lane >= o) inc += u;
    }
    __shared__ int wsum[8], wbase[8];
    if (lane == 31) wsum[warp] = inc;
    __syncthreads();
    if (t == 0) {
        int run = 0;
#pragma unroll
        for (int w = 0; w < 8; w++) { wbase[w] = run; run += wsum[w]; }
        g_nnz[row] = run < CAP ? run : CAP;
    }
    __syncthreads();

    int pos = wbase[warp] + inc - cnt;   // exclusive prefix
    int*   cr = g_cols + (size_t)row * CAP;
    float* vr = g_vals + (size_t)row * CAP;
    int base = t * 32;
#pragma unroll
    for (int i = 0; i < 8; i++) {
        float vv[4] = { v[i].x, v[i].y, v[i].z, v[i].w };
#pragma unroll
        for (int j = 0; j < 4; j++) {
            if (vv[j] > 0.f) {
                if (pos < CAP) { cr[pos] = base + i * 4 + j; vr[pos] = vv[j]; }
                pos++;
            }
        }
    }
}

// ---------------------------------------------------------------------------
// fp32 SGEMM, BMxBN tile, BK=8, 8x8 microtile, double-buffered, reg prefetch.
// THREADS = BM*BN/64. Smaller tiles -> more CTAs -> occupancy not grid-bound.
// ---------------------------------------------------------------------------
template<int BM, int BN>
__global__ __launch_bounds__(BM * BN / 64, 512 / (BM * BN / 64))
void sgemm_t(const float* __restrict__ A, const float* __restrict__ B,
             float* __restrict__ C, int K, int N)
{
    constexpr int THREADS = BM * BN / 64;
    constexpr int NLA = 2 * BM / THREADS;   // float4 A loads per thread
    constexpr int NLB = 2 * BN / THREADS;   // float4 B loads per thread
    constexpr int BN4 = BN / 4;

    __shared__ __align__(16) float As[2][8][BM + 4];
    __shared__ __align__(16) float Bs[2][8][BN + 4];

    int tid = threadIdx.x;
    int tx = tid % (BN / 8), ty = tid / (BN / 8);
    int m0 = blockIdx.y * BM, n0 = blockIdx.x * BN;

    const float* Ap[NLA]; int arow[NLA], aq[NLA];
#pragma unroll
    for (int i = 0; i < NLA; i++) {
        int e = tid + i * THREADS;
        arow[i] = e >> 1; aq[i] = (e & 1) * 4;
        Ap[i] = A + (size_t)(m0 + arow[i]) * K + aq[i];
    }
    const float* Bp[NLB]; int bk[NLB], bc[NLB];
#pragma unroll
    for (int i = 0; i < NLB; i++) {
        int f = tid + i * THREADS;
        bk[i] = f / BN4; bc[i] = (f % BN4) * 4;
        Bp[i] = B + (size_t)bk[i] * N + n0 + bc[i];
    }

    float4 avs[NLA], bvs[NLB];
#pragma unroll
    for (int i = 0; i < NLA; i++) avs[i] = *reinterpret_cast<const float4*>(Ap[i]);
#pragma unroll
    for (int i = 0; i < NLB; i++) bvs[i] = *reinterpret_cast<const float4*>(Bp[i]);
#pragma unroll
    for (int i = 0; i < NLA; i++) {
        As[0][aq[i] + 0][arow[i]] = avs[i].x; As[0][aq[i] + 1][arow[i]] = avs[i].y;
        As[0][aq[i] + 2][arow[i]] = avs[i].z; As[0][aq[i] + 3][arow[i]] = avs[i].w;
    }
#pragma unroll
    for (int i = 0; i < NLB; i++)
        *reinterpret_cast<float4*>(&Bs[0][bk[i]][bc[i]]) = bvs[i];
    __syncthreads();

    float acc[8][8];
#pragma unroll
    for (int i = 0; i < 8; i++)
#pragma unroll
        for (int j = 0; j < 8; j++) acc[i][j] = 0.f;

    int ktiles = K >> 3;
    for (int tk = 0; tk < ktiles; tk++) {
        int buf = tk & 1;
        if (tk + 1 < ktiles) {
#pragma unroll
            for (int i = 0; i < NLA; i++)
                avs[i] = *reinterpret_cast<const float4*>(Ap[i] + (tk + 1) * 8);
#pragma unroll
            for (int i = 0; i < NLB; i++)
                bvs[i] = *reinterpret_cast<const float4*>(Bp[i] + (size_t)(tk + 1) * 8 * N);
        }
#pragma unroll
        for (int k = 0; k < 8; k++) {
            float4 a0 = *reinterpret_cast<const float4*>(&As[buf][k][ty * 8]);
            float4 a1 = *reinterpret_cast<const float4*>(&As[buf][k][ty * 8 + 4]);
            float4 b0 = *reinterpret_cast<const float4*>(&Bs[buf][k][tx * 8]);
            float4 b1 = *reinterpret_cast<const float4*>(&Bs[buf][k][tx * 8 + 4]);
            float ra[8] = { a0.x, a0.y, a0.z, a0.w, a1.x, a1.y, a1.z, a1.w };
            float rb[8] = { b0.x, b0.y, b0.z, b0.w, b1.x, b1.y, b1.z, b1.w };
#pragma unroll
            for (int i = 0; i < 8; i++)
#pragma unroll
                for (int j = 0; j < 8; j++) acc[i][j] += ra[i] * rb[j];
        }
        if (tk + 1 < ktiles) {
            int nb = buf ^ 1;
#pragma unroll
            for (int i = 0; i < NLA; i++) {
                As[nb][aq[i] + 0][arow[i]] = avs[i].x; As[nb][aq[i] + 1][arow[i]] = avs[i].y;
                As[nb][aq[i] + 2][arow[i]] = avs[i].z; As[nb][aq[i] + 3][arow[i]] = avs[i].w;
            }
#pragma unroll
            for (int i = 0; i < NLB; i++)
                *reinterpret_cast<float4*>(&Bs[nb][bk[i]][bc[i]]) = bvs[i];
        }
        __syncthreads();
    }

#pragma unroll
    for (int i = 0; i < 8; i++) {
        size_t off = (size_t)(m0 + ty * 8 + i) * N + n0 + tx * 8;
        float4 o0 = { acc[i][0], acc[i][1], acc[i][2], acc[i][3] };
        float4 o1 = { acc[i][4], acc[i][5], acc[i][6], acc[i][7] };
        *reinterpret_cast<float4*>(&C[off])     = o0;
        *reinterpret_cast<float4*>(&C[off + 4]) = o1;
    }
}

// ---------------------------------------------------------------------------
// Barrier-free SpMM + bias + leaky. 64 lanes/row (float4), 2 rows per block.
// Uniform idx/val loads broadcast across the row group; unroll-4, 4 accums.
// ---------------------------------------------------------------------------
__global__ __launch_bounds__(128) void spmm_leaky(
    const float* __restrict__ T, const float* __restrict__ bias,
    float* __restrict__ O)
{
    int row = blockIdx.x * 2 + (threadIdx.x >> 6);
    int l   = threadIdx.x & 63;
    int nnz = g_nnz[row];
    const int*   cp = g_cols + (size_t)row * CAP;
    const float* vp = g_vals + (size_t)row * CAP;

    float4 a0 = {0,0,0,0}, a1 = {0,0,0,0}, a2 = {0,0,0,0}, a3 = {0,0,0,0};
    int k = 0;
    for (; k + 3 < nnz; k += 4) {
        int   c0 = cp[k], c1 = cp[k+1], c2 = cp[k+2], c3 = cp[k+3];
        float w0 = vp[k], w1 = vp[k+1], w2 = vp[k+2], w3 = vp[k+3];
        float4 v0 = reinterpret_cast<const float4*>(T + (size_t)c0 * DH)[l];
        float4 v1 = reinterpret_cast<const float4*>(T + (size_t)c1 * DH)[l];
        float4 v2 = reinterpret_cast<const float4*>(T + (size_t)c2 * DH)[l];
        float4 v3 = reinterpret_cast<const float4*>(T + (size_t)c3 * DH)[l];
        a0.x += w0*v0.x; a0.y += w0*v0.y; a0.z += w0*v0.z; a0.w += w0*v0.w;
        a1.x += w1*v1.x; a1.y += w1*v1.y; a1.z += w1*v1.z; a1.w += w1*v1.w;
        a2.x += w2*v2.x; a2.y += w2*v2.y; a2.z += w2*v2.z; a2.w += w2*v2.w;
        a3.x += w3*v3.x; a3.y += w3*v3.y; a3.z += w3*v3.z; a3.w += w3*v3.w;
    }
    for (; k < nnz; k++) {
        int c0 = cp[k]; float w0 = vp[k];
        float4 v0 = reinterpret_cast<const float4*>(T + (size_t)c0 * DH)[l];
        a0.x += w0*v0.x; a0.y += w0*v0.y; a0.z += w0*v0.z; a0.w += w0*v0.w;
    }
    float4 b = reinterpret_cast<const float4*>(bias)[l];
    float4 o;
    o.x = leaky(a0.x + a1.x + a2.x + a3.x + b.x);
    o.y = leaky(a0.y + a1.y + a2.y + a3.y + b.y);
    o.z = leaky(a0.z + a1.z + a2.z + a3.z + b.z);
    o.w = leaky(a0.w + a1.w + a2.w + a3.w + b.w);
    reinterpret_cast<float4*>(O + (size_t)row * DH)[l] = o;
}

// ---------------------------------------------------------------------------
// Warp-per-row scores: s1 = h.a1, s2 = h.a2 via shfl reduction.
// ---------------------------------------------------------------------------
__global__ __launch_bounds__(256) void scores_k(const float* __restrict__ a) {
    int row = blockIdx.x * 8 + (threadIdx.x >> 5);
    int l   = threadIdx.x & 31;
    float4 hv = reinterpret_cast<const float4*>(g_h + (size_t)row * DOUT)[l];
    float4 a1 = reinterpret_cast<const float4*>(a)[l];
    float4 a2 = reinterpret_cast<const float4*>(a + DOUT)[l];
    float r1 = hv.x*a1.x + hv.y*a1.y + hv.z*a1.z + hv.w*a1.w;
    float r2 = hv.x*a2.x + hv.y*a2.y + hv.z*a2.z + hv.w*a2.w;
#pragma unroll
    for (int o = 16; o > 0; o >>= 1) {
        r1 += __shfl_xor_sync(FULL, r1, o);
        r2 += __shfl_xor_sync(FULL, r2, o);
    }
    if (l == 0) { g_s1[row] = r1; g_s2[row] = r2; }
}

// Column means of h (fallback for the measure-zero empty-row case)
__global__ void hmean_k() {
    int c = blockIdx.x, t = threadIdx.x;
    float s = 0.f;
    for (int r = t; r < NN; r += 256) s += g_h[(size_t)r * DOUT + c];
    __shared__ float red[256];
    red[t] = s;
    __syncthreads();
    for (int ss = 128; ss > 0; ss >>= 1) {
        if (t < ss) red[t] += red[t + ss];
        __syncthreads();
    }
    if (t == 0) g_hmean[c] = red[0] / (float)NN;
}

// ---------------------------------------------------------------------------
// Warp-per-row sparse attention (exact match of dense masked softmax).
// 8 warps/block, shfl reductions, float4 h gathers, no block barriers.
// ---------------------------------------------------------------------------
__global__ __launch_bounds__(256) void attn_k(float* __restrict__ out) {
    int warp = threadIdx.x >> 5, l = threadIdx.x & 31;
    int row  = blockIdx.x * 8 + warp;
    int nnz  = g_nnz[row];

    __shared__ float sw[8][CAP];
    __shared__ int   sc[8][CAP];
    float* w = sw[warp];
    int*   c = sc[warp];

    float4 o;
    if (nnz == 0) {
        float4 hm = reinterpret_cast<const float4*>(g_hmean)[l];
        o.x = leaky(hm.x); o.y = leaky(hm.y); o.z = leaky(hm.z); o.w = leaky(hm.w);
    } else {
        float s1i = g_s1[row];
        const int* cp = g_cols + (size_t)row * CAP;
        float m = -3.0e38f;
        for (int k = l; k < nnz; k += 32) {
            int cj = cp[k];
            float e = leaky(s1i + g_s2[cj]);
            c[k] = cj; w[k] = e;
            m = fmaxf(m, e);
        }
        __syncwarp();
#pragma unroll
        for (int off = 16; off > 0; off >>= 1)
            m = fmaxf(m, __shfl_xor_sync(FULL, m, off));
        float s = 0.f;
        for (int k = l; k < nnz; k += 32) {
            float e = expf(w[k] - m);
            w[k] = e; s += e;
        }
        __syncwarp();
#pragma unroll
        for (int off = 16; off > 0; off >>= 1)
            s += __shfl_xor_sync(FULL, s, off);
        float inv = 1.f / s;

        float4 a0 = {0,0,0,0}, a1 = {0,0,0,0};
        int k = 0;
        for (; k + 1 < nnz; k += 2) {
            float w0 = w[k], w1 = w[k+1];
            float4 v0 = reinterpret_cast<const float4*>(g_h + (size_t)c[k]   * DOUT)[l];
            float4 v1 = reinterpret_cast<const float4*>(g_h + (size_t)c[k+1] * DOUT)[l];
            a0.x += w0*v0.x; a0.y += w0*v0.y; a0.z += w0*v0.z; a0.w += w0*v0.w;
            a1.x += w1*v1.x; a1.y += w1*v1.y; a1.z += w1*v1.z; a1.w += w1*v1.w;
        }
        if (k < nnz) {
            float w0 = w[k];
            float4 v0 = reinterpret_cast<const float4*>(g_h + (size_t)c[k] * DOUT)[l];
            a0.x += w0*v0.x; a0.y += w0*v0.y; a0.z += w0*v0.z; a0.w += w0*v0.w;
        }
        o.x = leaky((a0.x + a1.x) * inv);
        o.y = leaky((a0.y + a1.y) * inv);
        o.z = leaky((a0.z + a1.z) * inv);
        o.w = leaky((a0.w + a1.w) * inv);
    }
    // cols l*4..l*4+3; lanes 0-15 -> mu, lanes 16-31 -> logvar (split at 64)
    if (l < 16)
        *reinterpret_cast<float4*>(out + (size_t)row * 64 + l * 4) = o;
    else
        *reinterpret_cast<float4*>(out + (size_t)NN * 64 + (size_t)row * 64 + (l * 4 - 64)) = o;
}

// ---------------------------------------------------------------------------
extern "C" void kernel_launch(void* const* d_in, const int* in_sizes, int n_in,
                              void* d_out, int out_size)
{
    const float* x   = (const float*)d_in[0];
    const float* adj = (const float*)d_in[1];
    const float* W1  = (const float*)d_in[2];
    const float* b1  = (const float*)d_in[3];
    const float* W2  = (const float*)d_in[4];
    const float* b2  = (const float*)d_in[5];
    const float* Wg  = (const float*)d_in[6];
    const float* a   = (const float*)d_in[7];

    float *pA, *pB, *pH;
    cudaGetSymbolAddress((void**)&pA, g_bufA);
    cudaGetSymbolAddress((void**)&pB, g_bufB);
    cudaGetSymbolAddress((void**)&pH, g_h);

    build_csr<<<NN, 256>>>(adj);

    // t1 = x @ W1   (M=8192, N=256, K=512): 4x64 = 256 CTAs
    sgemm_t<128, 64><<<dim3(DH / 64, NN / 128), 128>>>(x, W1, pA, DIN, DH);
    // x1 = leaky(adj @ t1 + b1)
    spmm_leaky<<<NN / 2, 128>>>(pA, b1, pB);
    // t2 = x1 @ W2  (N=256, K=256): 256 CTAs
    sgemm_t<128, 64><<<dim3(DH / 64, NN / 128), 128>>>(pB, W2, pA, DH, DH);
    // x2 = leaky(adj @ t2 + b2)
    spmm_leaky<<<NN / 2, 128>>>(pA, b2, pB);
    // h = x2 @ Wg   (N=128, K=256): 2x128 = 256 CTAs with 64x64 tiles
    sgemm_t<64, 64><<<dim3(DOUT / 64, NN / 64), 64>>>(pB, Wg, pH, DH, DOUT);

    scores_k<<<NN / 8, 256>>>(a);
    hmean_k<<<DOUT, 256>>>();
    attn_k<<<NN / 8, 256>>>((float*)d_out);
}